// round 3
// baseline (speedup 1.0000x reference)
#include <cuda_runtime.h>
#include <math.h>

// AFT-full, separable-exponent rewrite.
//   Launch 1: q = sigmoid(xWq^T+bq); Z = [exp(k)*v | exp(k)]; P = exp(pos_bias)
//   Launch 2: per batch O = P @ Z ; out = q * num/den fused in epilogue
// f32x2 FFMA2 packed across M (adjacent rows), B stored column-duplicated,
// register double-buffered inner loop.

#define BSZ   4
#define SEQ   512
#define DIM   128
#define NROW  (BSZ * SEQ)      // 2048
#define ZN    256              // E*v | E

typedef unsigned long long ull;

__device__ float g_q[NROW * DIM];
__device__ float g_Z[NROW * ZN];
__device__ float g_P[SEQ * SEQ];

__device__ __forceinline__ void ffma2(ull &d, ull a, ull b) {
    asm("fma.rn.f32x2 %0, %1, %2, %0;" : "+l"(d) : "l"(a), "l"(b));
}
__device__ __forceinline__ float2 unpk(ull v) {
    float2 f; asm("mov.b64 {%0, %1}, %2;" : "=f"(f.x), "=f"(f.y) : "l"(v)); return f;
}

// ---------------------------------------------------------------------------
// Launch 1. Blocks 0..127: QKV projection, 32 rows x 64 e-cols per block.
//           Blocks 128..159: P = exp(pos_bias).
// ---------------------------------------------------------------------------
__global__ __launch_bounds__(256)
void proj_prep(const float* __restrict__ x,
               const float* __restrict__ Wq, const float* __restrict__ bq,
               const float* __restrict__ Wk, const float* __restrict__ bk,
               const float* __restrict__ Wv, const float* __restrict__ bv,
               const float* __restrict__ pos)
{
    const int blk = blockIdx.x;
    const int tid = threadIdx.x;

    if (blk >= 128) {                       // ---- P = exp(pos_bias) ----
        const int base = (blk - 128) * 8192;
        #pragma unroll
        for (int j = 0; j < 8; j++) {
            int i = base + (j * 256 + tid) * 4;
            float4 p = *(const float4*)&pos[i];
            float4 o;
            o.x = __expf(p.x); o.y = __expf(p.y);
            o.z = __expf(p.z); o.w = __expf(p.w);
            *(float4*)&g_P[i] = o;
        }
        return;
    }

    // ---- projection GEMM (32 rows x 64 e-cols), FFMA2 packed across M ----
    const int m0 = (blk >> 1) * 32;
    const int e0 = (blk & 1) * 64;

    __shared__ float As[32][34];                      // x [k][m] natural
    __shared__ float Bq[32][132], Bk2[32][132], Bv2[32][132];  // dup [k][2e]

    const int w  = tid >> 5;                // warp e-slice [e0+8w, +8)
    const int l  = tid & 31;
    const int mg = l >> 2;                  // m-pair group
    const int dg = l & 3;                   // e-col pair group

    ull aq[2][2] = {{0,0},{0,0}}, ak[2][2] = {{0,0},{0,0}}, av[2][2] = {{0,0},{0,0}};

    const int kk = tid & 31;                // loader
    const int s0 = tid >> 5;

    for (int k0 = 0; k0 < DIM; k0 += 32) {
        #pragma unroll
        for (int i = 0; i < 4; i++) {
            int mm = s0 + 8 * i;
            As[kk][mm] = x[(m0 + mm) * DIM + k0 + kk];
        }
        #pragma unroll
        for (int i = 0; i < 8; i++) {
            int ee = s0 + 8 * i;
            float q = Wq[(e0 + ee) * DIM + k0 + kk];
            float k = Wk[(e0 + ee) * DIM + k0 + kk];
            float v = Wv[(e0 + ee) * DIM + k0 + kk];
            Bq [kk][2*ee] = q; Bq [kk][2*ee+1] = q;
            Bk2[kk][2*ee] = k; Bk2[kk][2*ee+1] = k;
            Bv2[kk][2*ee] = v; Bv2[kk][2*ee+1] = v;
        }
        __syncthreads();
        const int bo = (w * 8 + dg * 2) * 2;
        #pragma unroll
        for (int k = 0; k < 32; k++) {
            ull a0 = *(const ull*)&As[k][2 * mg];
            ull a1 = *(const ull*)&As[k][2 * mg + 16];
            ulonglong2 q2 = *(const ulonglong2*)&Bq [k][bo];
            ulonglong2 k2 = *(const ulonglong2*)&Bk2[k][bo];
            ulonglong2 v2 = *(const ulonglong2*)&Bv2[k][bo];
            ffma2(aq[0][0], a0, q2.x); ffma2(aq[0][1], a0, q2.y);
            ffma2(aq[1][0], a1, q2.x); ffma2(aq[1][1], a1, q2.y);
            ffma2(ak[0][0], a0, k2.x); ffma2(ak[0][1], a0, k2.y);
            ffma2(ak[1][0], a1, k2.x); ffma2(ak[1][1], a1, k2.y);
            ffma2(av[0][0], a0, v2.x); ffma2(av[0][1], a0, v2.y);
            ffma2(av[1][0], a1, v2.x); ffma2(av[1][1], a1, v2.y);
        }
        __syncthreads();
    }

    // epilogue
    const int cb = e0 + w * 8 + dg * 2;     // first of 2 e-cols
    const float2 bqv = *(const float2*)&bq[cb];
    const float2 bkv = *(const float2*)&bk[cb];
    const float2 bvv = *(const float2*)&bv[cb];
    #pragma unroll
    for (int p = 0; p < 2; p++) {
        float2 qc0 = unpk(aq[p][0]), qc1 = unpk(aq[p][1]);
        float2 kc0 = unpk(ak[p][0]), kc1 = unpk(ak[p][1]);
        float2 vc0 = unpk(av[p][0]), vc1 = unpk(av[p][1]);
        int r0 = m0 + 2 * mg + 16 * p;
        #pragma unroll
        for (int r = 0; r < 2; r++) {
            int row = r0 + r;
            float qa = (r == 0) ? qc0.x : qc0.y;
            float qb = (r == 0) ? qc1.x : qc1.y;
            float ka = (r == 0) ? kc0.x : kc0.y;
            float kb = (r == 0) ? kc1.x : kc1.y;
            float va = (r == 0) ? vc0.x : vc0.y;
            float vb = (r == 0) ? vc1.x : vc1.y;
            float sx = 1.0f / (1.0f + __expf(-(qa + bqv.x)));
            float sy = 1.0f / (1.0f + __expf(-(qb + bqv.y)));
            float ex = __expf(ka + bkv.x);
            float ey = __expf(kb + bkv.y);
            va += bvv.x;  vb += bvv.y;
            *(float2*)&g_q[row * DIM + cb]      = make_float2(sx, sy);
            *(float2*)&g_Z[row * ZN + cb]       = make_float2(ex * va, ey * vb);
            *(float2*)&g_Z[row * ZN + DIM + cb] = make_float2(ex, ey);
        }
    }
}

// ---------------------------------------------------------------------------
// Launch 2. O = P @ Z per batch; out = q*num/den fused.
// Block: 32 m x 64 d (+den), 256 threads. grid = (2, 16, 4) = 128.
// Thread: 2 m-pairs x 2 d-cols x {num,den} = 16 f32x2 accumulators.
// Per k: 2 LDS.64 (A, natural pairs) + 2 LDS.128 (B dup) -> 8 FFMA2.
// ---------------------------------------------------------------------------
__global__ __launch_bounds__(256)
void aft_out(float* __restrict__ out)
{
    const int b  = blockIdx.z;
    const int m0 = blockIdx.y * 32;
    const int d0 = blockIdx.x * 64;
    const float* __restrict__ Zb = g_Z + (size_t)b * SEQ * ZN;

    __shared__ float As[32][34];            // P [k][m] natural layout
    __shared__ float Bn[32][132];           // Z num, duplicated [k][2d]
    __shared__ float Bd[32][132];           // Z den, duplicated [k][2d]

    const int tid = threadIdx.x;
    const int w  = tid >> 5;                // warp d-slice [d0+8w, +8)
    const int l  = tid & 31;
    const int mg = l >> 2;                  // m-pair group (rows 2mg,2mg+1 and +16)
    const int dg = l & 3;                   // d-col pair group

    ull accN[2][2] = {{0,0},{0,0}}, accD[2][2] = {{0,0},{0,0}};

    const int kk  = tid & 31;               // A loader
    const int s0  = tid >> 5;
    const int c4  = tid & 31;               // B loader: float4 slot
    const int kr0 = tid >> 5;

    const int bo = (w * 8 + dg * 2) * 2;    // dup-float offset of this thread's 2 cols

    for (int j0 = 0; j0 < SEQ; j0 += 32) {
        // --- stage A: 32k x 32m of P ---
        #pragma unroll
        for (int i = 0; i < 4; i++) {
            int mm = s0 + 8 * i;
            As[kk][mm] = g_P[(m0 + mm) * SEQ + j0 + kk];
        }
        // --- stage B: 32k x (64 num + 64 den), duplicated ---
        #pragma unroll
        for (int i = 0; i < 4; i++) {
            int kr = kr0 + 8 * i;
            const float* src = Zb + (j0 + kr) * ZN;
            if (c4 < 16) {
                float4 v = *(const float4*)(src + d0 + c4 * 4);
                *(float4*)&Bn[kr][c4 * 8]     = make_float4(v.x, v.x, v.y, v.y);
                *(float4*)&Bn[kr][c4 * 8 + 4] = make_float4(v.z, v.z, v.w, v.w);
            } else {
                int cc = c4 - 16;
                float4 v = *(const float4*)(src + 128 + d0 + cc * 4);
                *(float4*)&Bd[kr][cc * 8]     = make_float4(v.x, v.x, v.y, v.y);
                *(float4*)&Bd[kr][cc * 8 + 4] = make_float4(v.z, v.z, v.w, v.w);
            }
        }
        __syncthreads();

        // --- compute, register double-buffered over k ---
        ull a0 = *(const ull*)&As[0][2 * mg];
        ull a1 = *(const ull*)&As[0][2 * mg + 16];
        ulonglong2 n2 = *(const ulonglong2*)&Bn[0][bo];
        ulonglong2 e2 = *(const ulonglong2*)&Bd[0][bo];
        #pragma unroll
        for (int k = 0; k < 32; k++) {
            ull ca0 = a0, ca1 = a1;
            ulonglong2 cn = n2, ce = e2;
            if (k < 31) {
                a0 = *(const ull*)&As[k + 1][2 * mg];
                a1 = *(const ull*)&As[k + 1][2 * mg + 16];
                n2 = *(const ulonglong2*)&Bn[k + 1][bo];
                e2 = *(const ulonglong2*)&Bd[k + 1][bo];
            }
            ffma2(accN[0][0], ca0, cn.x); ffma2(accN[0][1], ca0, cn.y);
            ffma2(accN[1][0], ca1, cn.x); ffma2(accN[1][1], ca1, cn.y);
            ffma2(accD[0][0], ca0, ce.x); ffma2(accD[0][1], ca0, ce.y);
            ffma2(accD[1][0], ca1, ce.x); ffma2(accD[1][1], ca1, ce.y);
        }
        __syncthreads();
    }

    // --- fused epilogue: out = q * num / den ---
    const int cb = d0 + w * 8 + dg * 2;
    #pragma unroll
    for (int p = 0; p < 2; p++) {
        float2 nc0 = unpk(accN[p][0]), nc1 = unpk(accN[p][1]);
        float2 dc0 = unpk(accD[p][0]), dc1 = unpk(accD[p][1]);
        int r0 = m0 + 2 * mg + 16 * p;
        {
            int row = b * SEQ + r0;
            float2 q = *(const float2*)&g_q[row * DIM + cb];
            *(float2*)&out[row * DIM + cb] =
                make_float2(q.x * nc0.x / dc0.x, q.y * nc1.x / dc1.x);
        }
        {
            int row = b * SEQ + r0 + 1;
            float2 q = *(const float2*)&g_q[row * DIM + cb];
            *(float2*)&out[row * DIM + cb] =
                make_float2(q.x * nc0.y / dc0.y, q.y * nc1.y / dc1.y);
        }
    }
}

// ---------------------------------------------------------------------------
extern "C" void kernel_launch(void* const* d_in, const int* in_sizes, int n_in,
                              void* d_out, int out_size)
{
    const float* x   = (const float*)d_in[0];
    const float* Wq  = (const float*)d_in[1];
    const float* bq  = (const float*)d_in[2];
    const float* Wk  = (const float*)d_in[3];
    const float* bk  = (const float*)d_in[4];
    const float* Wv  = (const float*)d_in[5];
    const float* bv  = (const float*)d_in[6];
    const float* pos = (const float*)d_in[7];
    float* out = (float*)d_out;

    proj_prep<<<160, 256>>>(x, Wq, bq, Wk, bk, Wv, bv, pos);
    aft_out<<<dim3(2, 16, 4), 256>>>(out);
}

// round 6
// speedup vs baseline: 3.0578x; 3.0578x over previous
#include <cuda_runtime.h>
#include <cuda_bf16.h>
#include <math.h>
#include <stdint.h>

// AFT-full via separable exponent + mma.sync bf16 split-GEMM (3-pass Markidis).
//   L1 proj_prep: q=sigmoid(xWq^T+bq); Z=[exp(k)*v|exp(k)] fp32; Ph/Pl=split(exp(pos))
//   L2 transZ:    Zt[b][d][j] = Z[b][j][d], split into bf16 hi/lo
//   L3 aft_mma:   O2 = P @ Z on tensor cores (HMMA), ratio fused in epilogue

#define BSZ   4
#define SEQ   512
#define DIM   128
#define NROW  (BSZ * SEQ)
#define ZN    256

typedef unsigned long long ull;

__device__ __align__(16) float         g_q  [NROW * DIM];
__device__ __align__(16) float         g_Z  [NROW * ZN];
__device__ __align__(16) __nv_bfloat16 g_Ph [SEQ * SEQ];
__device__ __align__(16) __nv_bfloat16 g_Pl [SEQ * SEQ];
__device__ __align__(16) __nv_bfloat16 g_Zth[BSZ * ZN * SEQ];
__device__ __align__(16) __nv_bfloat16 g_Ztl[BSZ * ZN * SEQ];

// ---------------- portable PTX helpers (sm_80+ features only) --------------
__device__ __forceinline__ uint32_t smem_u32(const void* p) {
    uint32_t a;
    asm("{ .reg .u64 t; cvta.to.shared.u64 t, %1; cvt.u32.u64 %0, t; }" : "=r"(a) : "l"(p));
    return a;
}
#define SWZ64(x) ((x) ^ (((x) >> 3) & 0x30))

__device__ __forceinline__ void ldsm4(uint32_t* r, uint32_t addr) {
    asm volatile("ldmatrix.sync.aligned.m8n8.x4.shared.b16 {%0,%1,%2,%3}, [%4];"
        : "=r"(r[0]), "=r"(r[1]), "=r"(r[2]), "=r"(r[3]) : "r"(addr));
}
__device__ __forceinline__ void mma16816(float* c, const uint32_t* a, const uint32_t* b) {
    asm volatile("mma.sync.aligned.m16n8k16.row.col.f32.bf16.bf16.f32 "
        "{%0,%1,%2,%3}, {%4,%5,%6,%7}, {%8,%9}, {%0,%1,%2,%3};"
        : "+f"(c[0]), "+f"(c[1]), "+f"(c[2]), "+f"(c[3])
        : "r"(a[0]), "r"(a[1]), "r"(a[2]), "r"(a[3]), "r"(b[0]), "r"(b[1]));
}
__device__ __forceinline__ void cpa16(uint32_t s, const void* g) {
    asm volatile("cp.async.ca.shared.global [%0], [%1], 16;" :: "r"(s), "l"(g) : "memory");
}

__device__ __forceinline__ void ffma2(ull &d, ull a, ull b) {
    asm("fma.rn.f32x2 %0, %1, %2, %0;" : "+l"(d) : "l"(a), "l"(b));
}
__device__ __forceinline__ float2 unpk(ull v) {
    float2 f; asm("mov.b64 {%0, %1}, %2;" : "=f"(f.x), "=f"(f.y) : "l"(v)); return f;
}

// ---------------------------------------------------------------------------
// Launch 1. Blocks 0..127: QKV projection (round-2 proven code).
//           Blocks 128..159: Ph/Pl = bf16-split(exp(pos_bias)).
// ---------------------------------------------------------------------------
__global__ __launch_bounds__(256)
void proj_prep(const float* __restrict__ x,
               const float* __restrict__ Wq, const float* __restrict__ bq,
               const float* __restrict__ Wk, const float* __restrict__ bk,
               const float* __restrict__ Wv, const float* __restrict__ bv,
               const float* __restrict__ pos)
{
    const int blk = blockIdx.x;
    const int tid = threadIdx.x;

    if (blk >= 128) {                       // ---- Ph/Pl = split(exp(pos)) ----
        const int base = (blk - 128) * 8192;
        #pragma unroll
        for (int j = 0; j < 8; j++) {
            int i = base + (j * 256 + tid) * 4;
            float4 p = *(const float4*)&pos[i];
            float e0 = __expf(p.x), e1 = __expf(p.y), e2 = __expf(p.z), e3 = __expf(p.w);
            __nv_bfloat16 h0 = __float2bfloat16(e0), h1 = __float2bfloat16(e1);
            __nv_bfloat16 h2 = __float2bfloat16(e2), h3 = __float2bfloat16(e3);
            __nv_bfloat16 l0 = __float2bfloat16(e0 - __bfloat162float(h0));
            __nv_bfloat16 l1 = __float2bfloat16(e1 - __bfloat162float(h1));
            __nv_bfloat16 l2 = __float2bfloat16(e2 - __bfloat162float(h2));
            __nv_bfloat16 l3 = __float2bfloat16(e3 - __bfloat162float(h3));
            ((__nv_bfloat162*)g_Ph)[i/2]     = __nv_bfloat162(h0, h1);
            ((__nv_bfloat162*)g_Ph)[i/2 + 1] = __nv_bfloat162(h2, h3);
            ((__nv_bfloat162*)g_Pl)[i/2]     = __nv_bfloat162(l0, l1);
            ((__nv_bfloat162*)g_Pl)[i/2 + 1] = __nv_bfloat162(l2, l3);
        }
        return;
    }

    // ---- projection GEMM (32 rows x 64 e-cols), FFMA2 packed across D ----
    const int m0 = (blk >> 1) * 32;
    const int e0 = (blk & 1) * 64;

    __shared__ float As2[32][66];
    __shared__ float Bq[32][66], Bk2[32][66], Bv2[32][66];

    const int w  = tid >> 5;
    const int l  = tid & 31;
    const int mg = l >> 2;
    const int dg = l & 3;

    ull aq[4] = {0,0,0,0}, ak[4] = {0,0,0,0}, av[4] = {0,0,0,0};

    const int kk = tid & 31;
    const int s0 = tid >> 5;

    for (int k0 = 0; k0 < DIM; k0 += 32) {
        #pragma unroll
        for (int i = 0; i < 4; i++) {
            int mm = s0 + 8 * i;
            float v = x[(m0 + mm) * DIM + k0 + kk];
            As2[kk][2 * mm]     = v;
            As2[kk][2 * mm + 1] = v;
        }
        #pragma unroll
        for (int i = 0; i < 8; i++) {
            int ee = s0 + 8 * i;
            Bq [kk][ee] = Wq[(e0 + ee) * DIM + k0 + kk];
            Bk2[kk][ee] = Wk[(e0 + ee) * DIM + k0 + kk];
            Bv2[kk][ee] = Wv[(e0 + ee) * DIM + k0 + kk];
        }
        __syncthreads();
        #pragma unroll
        for (int k = 0; k < 32; k++) {
            ull bq2 = *(ull*)&Bq [k][w * 8 + dg * 2];
            ull bk2 = *(ull*)&Bk2[k][w * 8 + dg * 2];
            ull bv2 = *(ull*)&Bv2[k][w * 8 + dg * 2];
            ull a0 = *(ull*)&As2[k][(mg * 4 + 0) * 2];
            ull a1 = *(ull*)&As2[k][(mg * 4 + 1) * 2];
            ull a2 = *(ull*)&As2[k][(mg * 4 + 2) * 2];
            ull a3 = *(ull*)&As2[k][(mg * 4 + 3) * 2];
            ffma2(aq[0], a0, bq2); ffma2(ak[0], a0, bk2); ffma2(av[0], a0, bv2);
            ffma2(aq[1], a1, bq2); ffma2(ak[1], a1, bk2); ffma2(av[1], a1, bv2);
            ffma2(aq[2], a2, bq2); ffma2(ak[2], a2, bk2); ffma2(av[2], a2, bv2);
            ffma2(aq[3], a3, bq2); ffma2(ak[3], a3, bk2); ffma2(av[3], a3, bv2);
        }
        __syncthreads();
    }

    const int e2i = e0 + w * 8 + dg * 2;
    const float2 bq_v = *(const float2*)&bq[e2i];
    const float2 bk_v = *(const float2*)&bk[e2i];
    const float2 bv_v = *(const float2*)&bv[e2i];
    #pragma unroll
    for (int i = 0; i < 4; i++) {
        const int row = m0 + mg * 4 + i;
        float2 qv = unpk(aq[i]);
        float2 kv = unpk(ak[i]);
        float2 vv = unpk(av[i]);
        qv.x = 1.0f / (1.0f + __expf(-(qv.x + bq_v.x)));
        qv.y = 1.0f / (1.0f + __expf(-(qv.y + bq_v.y)));
        float ex = __expf(kv.x + bk_v.x);
        float ey = __expf(kv.y + bk_v.y);
        vv.x += bv_v.x;  vv.y += bv_v.y;
        *(float2*)&g_q[row * DIM + e2i]      = qv;
        *(float2*)&g_Z[row * ZN + e2i]       = make_float2(ex * vv.x, ey * vv.y);
        *(float2*)&g_Z[row * ZN + DIM + e2i] = make_float2(ex, ey);
    }
}

// ---------------------------------------------------------------------------
// Launch 2. Zt[b][d][j] = Z[b][j][d], bf16 split. 64x64 tiles via SMEM.
// grid = (4 d-tiles, 8 j-tiles, 4 batches) = 128, 256 threads.
// ---------------------------------------------------------------------------
__global__ __launch_bounds__(256)
void transZ()
{
    __shared__ float T[64][65];
    const int d0 = blockIdx.x * 64;
    const int j0 = blockIdx.y * 64;
    const int b  = blockIdx.z;
    const int tid = threadIdx.x;

    #pragma unroll
    for (int it = 0; it < 4; it++) {
        int idx = it * 256 + tid;
        int r = idx >> 4, c4 = idx & 15;
        float4 v = *(const float4*)&g_Z[((size_t)(b * SEQ + j0 + r)) * ZN + d0 + c4 * 4];
        T[r][c4*4+0] = v.x; T[r][c4*4+1] = v.y; T[r][c4*4+2] = v.z; T[r][c4*4+3] = v.w;
    }
    __syncthreads();

    #pragma unroll
    for (int it = 0; it < 8; it++) {
        int idx = it * 256 + tid;
        int dr = idx >> 5, jc = idx & 31;
        float v0 = T[jc * 2][dr];
        float v1 = T[jc * 2 + 1][dr];
        __nv_bfloat16 h0 = __float2bfloat16(v0), h1 = __float2bfloat16(v1);
        __nv_bfloat16 l0 = __float2bfloat16(v0 - __bfloat162float(h0));
        __nv_bfloat16 l1 = __float2bfloat16(v1 - __bfloat162float(h1));
        size_t o2 = (size_t)(b * ZN + d0 + dr) * (SEQ / 2) + (j0 >> 1) + jc;
        ((__nv_bfloat162*)g_Zth)[o2] = __nv_bfloat162(h0, h1);
        ((__nv_bfloat162*)g_Ztl)[o2] = __nv_bfloat162(l0, l1);
    }
}

// ---------------------------------------------------------------------------
// Launch 3. O2 = P @ Z via mma.sync bf16, 3-pass split, ratio fused.
// CTA: 64m x (32 num-d + 32 den-d), K=512 in 16 stages of 32.
// 8 warps = 2(m) x 4(n16); warps n0,n1 = num cols, n2,n3 = den cols.
// Stage SMEM: Ah|Al|Bh|Bl, 64 rows x 32 bf16 (64B rows, SW64), double-buffered.
// grid = (4 d-tiles, 8 m-tiles, 4 b) = 128 CTAs, 256 threads.
// ---------------------------------------------------------------------------
__global__ __launch_bounds__(256, 1)
void aft_mma(float* __restrict__ out)
{
    __shared__ __align__(128) char stg[2][16384];
    __shared__ float den[64][34];

    const int tid  = threadIdx.x;
    const int wid  = tid >> 5, lane = tid & 31;
    const int mw   = wid >> 2, nw = wid & 3;

    const int d0 = blockIdx.x * 32;
    const int m0 = blockIdx.y * 64;
    const int b  = blockIdx.z;

    const uint32_t sm0 = smem_u32(stg[0]);
    const uint32_t sm1 = smem_u32(stg[1]);

    // ldmatrix lane maps (standard m16n8k16 fragment addressing)
    const int am  = (lane & 7) + ((lane >> 3) & 1) * 8;   // A row within m16
    const int akb = (lane >> 4) * 8;                      // A k-base (elements)
    const int bn  = (lane & 7) + ((lane >> 4) & 1) * 8;   // B row within n16
    const int bkb = ((lane >> 3) & 1) * 8;                // B k-base

    float c[2][2][4] = {};

    auto load_stage = [&](int s) {
        const uint32_t sb = (s & 1) ? sm1 : sm0;
        const int k0 = s * 32;
        #pragma unroll
        for (int i = 0; i < 4; i++) {
            int cch  = tid + i * 256;          // [0,1024): 4 tiles x 256 chunks
            int tile = cch >> 8;
            int cc   = cch & 255;
            int row  = cc >> 2, c16 = cc & 3;
            uint32_t so = sb + tile * 4096 + SWZ64(row * 64 + c16 * 16);
            const __nv_bfloat16* src;
            int grow;
            if (tile < 2) {
                grow = m0 + row;
                src = (tile == 0) ? g_Ph : g_Pl;
            } else {
                int rowZ = (row < 32) ? d0 + row : 96 + d0 + row;   // den half: +128
                grow = b * ZN + rowZ;
                src = (tile == 2) ? g_Zth : g_Ztl;
            }
            cpa16(so, src + (size_t)grow * SEQ + k0 + c16 * 8);
        }
        asm volatile("cp.async.commit_group;" ::: "memory");
    };

    load_stage(0);

    for (int s = 0; s < 16; s++) {
        asm volatile("cp.async.wait_group 0;" ::: "memory");
        __syncthreads();
        if (s < 15) load_stage(s + 1);
        const uint32_t sb = (s & 1) ? sm1 : sm0;
        #pragma unroll
        for (int kk = 0; kk < 2; kk++) {
            uint32_t ah[2][4], al[2][4], bh[4], bl[4];
            #pragma unroll
            for (int ms = 0; ms < 2; ms++) {
                int rowA = mw * 32 + ms * 16 + am;
                uint32_t off = SWZ64(rowA * 64 + kk * 32 + akb * 2);
                ldsm4(ah[ms], sb + off);
                ldsm4(al[ms], sb + 4096 + off);
            }
            {
                int rowB = nw * 16 + bn;
                uint32_t off = SWZ64(rowB * 64 + kk * 32 + bkb * 2);
                ldsm4(bh, sb + 8192 + off);
                ldsm4(bl, sb + 12288 + off);
            }
            #pragma unroll
            for (int ms = 0; ms < 2; ms++)
                #pragma unroll
                for (int ns = 0; ns < 2; ns++) {
                    mma16816(c[ms][ns], ah[ms], bh + 2 * ns);
                    mma16816(c[ms][ns], ah[ms], bl + 2 * ns);
                    mma16816(c[ms][ns], al[ms], bh + 2 * ns);
                }
        }
        __syncthreads();
    }

    // ---- fused epilogue: den warps publish, num warps write q*num/den ----
    if (nw >= 2) {
        #pragma unroll
        for (int ms = 0; ms < 2; ms++)
            #pragma unroll
            for (int ns = 0; ns < 2; ns++) {
                int dr = (nw - 2) * 16 + ns * 8 + 2 * (lane & 3);
                int r  = mw * 32 + ms * 16 + (lane >> 2);
                *(float2*)&den[r][dr]     = make_float2(c[ms][ns][0], c[ms][ns][1]);
                *(float2*)&den[r + 8][dr] = make_float2(c[ms][ns][2], c[ms][ns][3]);
            }
    }
    __syncthreads();
    if (nw < 2) {
        #pragma unroll
        for (int ms = 0; ms < 2; ms++)
            #pragma unroll
            for (int ns = 0; ns < 2; ns++) {
                int dr = nw * 16 + ns * 8 + 2 * (lane & 3);
                int r  = mw * 32 + ms * 16 + (lane >> 2);
                #pragma unroll
                for (int h = 0; h < 2; h++) {
                    int rr   = r + h * 8;
                    int grow = b * SEQ + m0 + rr;
                    float2 dn = *(float2*)&den[rr][dr];
                    float2 q  = *(const float2*)&g_q[(size_t)grow * DIM + d0 + dr];
                    float2 o;
                    o.x = q.x * c[ms][ns][2 * h]     / dn.x;
                    o.y = q.y * c[ms][ns][2 * h + 1] / dn.y;
                    *(float2*)&out[(size_t)grow * DIM + d0 + dr] = o;
                }
            }
    }
}

// ---------------------------------------------------------------------------
extern "C" void kernel_launch(void* const* d_in, const int* in_sizes, int n_in,
                              void* d_out, int out_size)
{
    const float* x   = (const float*)d_in[0];
    const float* Wq  = (const float*)d_in[1];
    const float* bq  = (const float*)d_in[2];
    const float* Wk  = (const float*)d_in[3];
    const float* bk  = (const float*)d_in[4];
    const float* Wv  = (const float*)d_in[5];
    const float* bv  = (const float*)d_in[6];
    const float* pos = (const float*)d_in[7];
    float* out = (float*)d_out;

    proj_prep<<<160, 256>>>(x, Wq, bq, Wk, bk, Wv, bv, pos);
    transZ<<<dim3(4, 8, 4), 256>>>();
    aft_mma<<<dim3(4, 8, 4), 256>>>(out);
}

// round 8
// speedup vs baseline: 3.3116x; 1.0830x over previous
#include <cuda_runtime.h>
#include <cuda_bf16.h>
#include <math.h>
#include <stdint.h>

// AFT-full via separable exponent, all GEMMs on tensor cores (mma.sync bf16,
// 3-pass Markidis split):
//   L1 split_inputs: xh/xl, Wh/Wl (qkv concat), Ph/Pl = split(exp(pos))
//   L2 proj_mma:     qkv = x@W^T+b; epilogue: g_q = sigmoid(q), g_Z=[E*v|E] fp32
//   L3 transZ:       Zt[b][d][j] = Z[b][j][d], bf16 hi/lo split
//   L4 aft_mma:      O2 = P @ Z on HMMA, out = q*num/den fused

#define BSZ   4
#define SEQ   512
#define DIM   128
#define NROW  (BSZ * SEQ)
#define ZN    256

typedef unsigned long long ull;

__device__ __align__(16) float         g_q  [NROW * DIM];
__device__ __align__(16) float         g_Z  [NROW * ZN];
__device__ __align__(16) __nv_bfloat16 g_xh [NROW * DIM];
__device__ __align__(16) __nv_bfloat16 g_xl [NROW * DIM];
__device__ __align__(16) __nv_bfloat16 g_Wh [384 * DIM];
__device__ __align__(16) __nv_bfloat16 g_Wl [384 * DIM];
__device__ __align__(16) __nv_bfloat16 g_Ph [SEQ * SEQ];
__device__ __align__(16) __nv_bfloat16 g_Pl [SEQ * SEQ];
__device__ __align__(16) __nv_bfloat16 g_Zth[BSZ * ZN * SEQ];
__device__ __align__(16) __nv_bfloat16 g_Ztl[BSZ * ZN * SEQ];

// ---------------- portable PTX helpers (sm_80+ features only) --------------
__device__ __forceinline__ uint32_t smem_u32(const void* p) {
    uint32_t a;
    asm("{ .reg .u64 t; cvta.to.shared.u64 t, %1; cvt.u32.u64 %0, t; }" : "=r"(a) : "l"(p));
    return a;
}
#define SWZ64(x) ((x) ^ (((x) >> 3) & 0x30))

__device__ __forceinline__ void ldsm4(uint32_t* r, uint32_t addr) {
    asm volatile("ldmatrix.sync.aligned.m8n8.x4.shared.b16 {%0,%1,%2,%3}, [%4];"
        : "=r"(r[0]), "=r"(r[1]), "=r"(r[2]), "=r"(r[3]) : "r"(addr));
}
__device__ __forceinline__ void ldsm2(uint32_t* r, uint32_t addr) {
    asm volatile("ldmatrix.sync.aligned.m8n8.x2.shared.b16 {%0,%1}, [%2];"
        : "=r"(r[0]), "=r"(r[1]) : "r"(addr));
}
__device__ __forceinline__ void mma16816(float* c, const uint32_t* a, const uint32_t* b) {
    asm volatile("mma.sync.aligned.m16n8k16.row.col.f32.bf16.bf16.f32 "
        "{%0,%1,%2,%3}, {%4,%5,%6,%7}, {%8,%9}, {%0,%1,%2,%3};"
        : "+f"(c[0]), "+f"(c[1]), "+f"(c[2]), "+f"(c[3])
        : "r"(a[0]), "r"(a[1]), "r"(a[2]), "r"(a[3]), "r"(b[0]), "r"(b[1]));
}
__device__ __forceinline__ void cpa16(uint32_t s, const void* g) {
    asm volatile("cp.async.ca.shared.global [%0], [%1], 16;" :: "r"(s), "l"(g) : "memory");
}

__device__ __forceinline__ void split_store(__nv_bfloat16* H, __nv_bfloat16* L,
                                            size_t e, float4 v) {
    float a0 = v.x, a1 = v.y, a2 = v.z, a3 = v.w;
    __nv_bfloat16 h0 = __float2bfloat16(a0), h1 = __float2bfloat16(a1);
    __nv_bfloat16 h2 = __float2bfloat16(a2), h3 = __float2bfloat16(a3);
    __nv_bfloat16 l0 = __float2bfloat16(a0 - __bfloat162float(h0));
    __nv_bfloat16 l1 = __float2bfloat16(a1 - __bfloat162float(h1));
    __nv_bfloat16 l2 = __float2bfloat16(a2 - __bfloat162float(h2));
    __nv_bfloat16 l3 = __float2bfloat16(a3 - __bfloat162float(h3));
    *(__nv_bfloat162*)&H[e]     = __nv_bfloat162(h0, h1);
    *(__nv_bfloat162*)&H[e + 2] = __nv_bfloat162(h2, h3);
    *(__nv_bfloat162*)&L[e]     = __nv_bfloat162(l0, l1);
    *(__nv_bfloat162*)&L[e + 2] = __nv_bfloat162(l2, l3);
}

// ---------------------------------------------------------------------------
// Launch 1. Elementwise bf16 hi/lo splits: x, W(qkv concat), exp(pos).
// grid = 560 x 256, one float4 per thread.
// ---------------------------------------------------------------------------
__global__ __launch_bounds__(256)
void split_inputs(const float* __restrict__ x,
                  const float* __restrict__ Wq, const float* __restrict__ Wk,
                  const float* __restrict__ Wv, const float* __restrict__ pos)
{
    int idx = blockIdx.x * 256 + threadIdx.x;
    if (idx < 65536) {                      // x: 262144 elements
        float4 v = ((const float4*)x)[idx];
        split_store(g_xh, g_xl, (size_t)idx * 4, v);
    } else if (idx < 131072) {              // exp(pos): 262144 elements
        int i = idx - 65536;
        float4 p = ((const float4*)pos)[i];
        float4 e;
        e.x = __expf(p.x); e.y = __expf(p.y); e.z = __expf(p.z); e.w = __expf(p.w);
        split_store(g_Ph, g_Pl, (size_t)i * 4, e);
    } else if (idx < 143360) {              // W concat: 49152 elements
        int i = idx - 131072;
        int e = i * 4;
        int mat = e >> 14;
        int off = e & 16383;
        const float* W = (mat == 0) ? Wq : (mat == 1) ? Wk : Wv;
        float4 v = *(const float4*)&W[off];
        split_store(g_Wh, g_Wl, (size_t)e, v);
    }
}

// ---------------------------------------------------------------------------
// Launch 2. Projection GEMM on tensor cores.
// C[2048 x 384] = x @ [Wq|Wk|Wv]^T, 3-pass bf16 split, K=128 in 4 stages.
// CTA: 64m x 96n where n = matched d-slice {q: d0..d0+32, k: +128, v: +256}.
// Epilogue: q->sigmoid->g_q;  E=exp(k+bk), V=v+bv exchanged via SMEM ->
//           g_Z[m][d0+dc]=E*V, g_Z[m][128+d0+dc]=E.
// 8 warps = 2(m) x 4(n24: 3 n8-frags). grid = (4 dslices, 32 mtiles).
// Stage SMEM: Ah|Al [64][32], Bh|Bl [96][32] = 20480 B, double buffered.
// ---------------------------------------------------------------------------
__global__ __launch_bounds__(256, 1)
void proj_mma(const float* __restrict__ bq, const float* __restrict__ bk,
              const float* __restrict__ bv)
{
    __shared__ __align__(128) char arena[40960];

    const int tid = threadIdx.x;
    const int wid = tid >> 5, lane = tid & 31;
    const int mw  = wid >> 2, nw = wid & 3;
    const int d0  = blockIdx.x * 32;
    const int m0  = blockIdx.y * 64;

    const uint32_t sm0 = smem_u32(arena);
    const uint32_t sm1 = sm0 + 20480;

    const int am  = (lane & 7) + ((lane >> 3) & 1) * 8;
    const int akb = (lane >> 4) * 8;
    const int bn  = (lane & 7) + ((lane >> 4) & 1) * 8;
    const int bkb = ((lane >> 3) & 1) * 8;

    float c[2][3][4] = {};

    auto load_stage = [&](int s) {
        const uint32_t sb = (s & 1) ? sm1 : sm0;
        const int k0 = s * 32;
        #pragma unroll
        for (int i = 0; i < 5; i++) {
            int cch = tid + i * 256;          // [0,1280)
            const __nv_bfloat16* src;
            uint32_t so; size_t go;
            if (cch < 512) {                  // A: xh/xl [64][32]
                int hl = cch >> 8, cc = cch & 255;
                int row = cc >> 2, c16 = cc & 3;
                so = sb + hl * 4096 + SWZ64(row * 64 + c16 * 16);
                src = hl ? g_xl : g_xh;
                go = (size_t)(m0 + row) * 128 + k0 + c16 * 8;
            } else {                          // B: Wh/Wl [96][32]
                int v2 = cch - 512;           // [0,768)
                int hl = v2 >= 384, cc = hl ? v2 - 384 : v2;
                int row = cc >> 2, c16 = cc & 3;
                so = sb + 8192 + hl * 6144 + SWZ64(row * 64 + c16 * 16);
                src = hl ? g_Wl : g_Wh;
                go = (size_t)((row >> 5) * 128 + d0 + (row & 31)) * 128 + k0 + c16 * 8;
            }
            cpa16(so, src + go);
        }
        asm volatile("cp.async.commit_group;" ::: "memory");
    };

    load_stage(0);

    for (int s = 0; s < 4; s++) {
        asm volatile("cp.async.wait_group 0;" ::: "memory");
        __syncthreads();
        if (s < 3) load_stage(s + 1);
        const uint32_t sb = (s & 1) ? sm1 : sm0;
        #pragma unroll
        for (int kk = 0; kk < 2; kk++) {
            uint32_t ah[2][4], al[2][4], bh[6], bl[6];
            #pragma unroll
            for (int ms = 0; ms < 2; ms++) {
                int rowA = mw * 32 + ms * 16 + am;
                uint32_t off = SWZ64(rowA * 64 + kk * 32 + akb * 2);
                ldsm4(ah[ms], sb + off);
                ldsm4(al[ms], sb + 4096 + off);
            }
            {
                int rowB = nw * 24 + bn;
                uint32_t off4 = SWZ64(rowB * 64 + kk * 32 + bkb * 2);
                ldsm4(bh, sb + 8192 + off4);
                ldsm4(bl, sb + 14336 + off4);
                int rowB2 = nw * 24 + 16 + (lane & 7);
                uint32_t off2 = SWZ64(rowB2 * 64 + kk * 32 + ((lane >> 3) & 1) * 16);
                ldsm2(bh + 4, sb + 8192 + off2);
                ldsm2(bl + 4, sb + 14336 + off2);
            }
            #pragma unroll
            for (int ms = 0; ms < 2; ms++)
                #pragma unroll
                for (int nf = 0; nf < 3; nf++) {
                    mma16816(c[ms][nf], ah[ms], bh + 2 * nf);
                    mma16816(c[ms][nf], ah[ms], bl + 2 * nf);
                    mma16816(c[ms][nf], al[ms], bh + 2 * nf);
                }
        }
        __syncthreads();
    }

    // ---- epilogue: reuse arena as E/V exchange buffers ----
    float (*Ebuf)[33] = (float(*)[33])arena;
    float (*Vbuf)[33] = (float(*)[33])(arena + 8448);

    #pragma unroll
    for (int ms = 0; ms < 2; ms++)
        #pragma unroll
        for (int nf = 0; nf < 3; nf++) {
            int ncl = nw * 24 + nf * 8;
            int region = ncl >> 5;
            int dcol = (ncl & 31) + 2 * (lane & 3);
            int r0 = mw * 32 + ms * 16 + (lane >> 2);
            #pragma unroll
            for (int h = 0; h < 2; h++) {
                int r = r0 + 8 * h;
                float v0 = c[ms][nf][2 * h], v1 = c[ms][nf][2 * h + 1];
                int d = d0 + dcol;
                if (region == 0) {
                    float s0 = 1.0f / (1.0f + __expf(-(v0 + bq[d])));
                    float s1 = 1.0f / (1.0f + __expf(-(v1 + bq[d + 1])));
                    *(float2*)&g_q[(size_t)(m0 + r) * 128 + d] = make_float2(s0, s1);
                } else if (region == 1) {
                    Ebuf[r][dcol]     = __expf(v0 + bk[d]);
                    Ebuf[r][dcol + 1] = __expf(v1 + bk[d + 1]);
                } else {
                    Vbuf[r][dcol]     = v0 + bv[d];
                    Vbuf[r][dcol + 1] = v1 + bv[d + 1];
                }
            }
        }
    __syncthreads();

    for (int idx = tid; idx < 1024; idx += 256) {
        int r = idx >> 4, dc2 = (idx & 15) * 2;
        float e0 = Ebuf[r][dc2], e1 = Ebuf[r][dc2 + 1];
        float w0 = Vbuf[r][dc2], w1 = Vbuf[r][dc2 + 1];
        size_t base = (size_t)(m0 + r) * 256 + d0;
        *(float2*)&g_Z[base + dc2]       = make_float2(e0 * w0, e1 * w1);
        *(float2*)&g_Z[base + 128 + dc2] = make_float2(e0, e1);
    }
}

// ---------------------------------------------------------------------------
// Launch 3. Zt[b][d][j] = Z[b][j][d], bf16 split. (round-6 proven)
// ---------------------------------------------------------------------------
__global__ __launch_bounds__(256)
void transZ()
{
    __shared__ float T[64][65];
    const int d0 = blockIdx.x * 64;
    const int j0 = blockIdx.y * 64;
    const int b  = blockIdx.z;
    const int tid = threadIdx.x;

    #pragma unroll
    for (int it = 0; it < 4; it++) {
        int idx = it * 256 + tid;
        int r = idx >> 4, c4 = idx & 15;
        float4 v = *(const float4*)&g_Z[((size_t)(b * SEQ + j0 + r)) * ZN + d0 + c4 * 4];
        T[r][c4*4+0] = v.x; T[r][c4*4+1] = v.y; T[r][c4*4+2] = v.z; T[r][c4*4+3] = v.w;
    }
    __syncthreads();

    #pragma unroll
    for (int it = 0; it < 8; it++) {
        int idx = it * 256 + tid;
        int dr = idx >> 5, jc = idx & 31;
        float v0 = T[jc * 2][dr];
        float v1 = T[jc * 2 + 1][dr];
        __nv_bfloat16 h0 = __float2bfloat16(v0), h1 = __float2bfloat16(v1);
        __nv_bfloat16 l0 = __float2bfloat16(v0 - __bfloat162float(h0));
        __nv_bfloat16 l1 = __float2bfloat16(v1 - __bfloat162float(h1));
        size_t o2 = (size_t)(b * ZN + d0 + dr) * (SEQ / 2) + (j0 >> 1) + jc;
        ((__nv_bfloat162*)g_Zth)[o2] = __nv_bfloat162(h0, h1);
        ((__nv_bfloat162*)g_Ztl)[o2] = __nv_bfloat162(l0, l1);
    }
}

// ---------------------------------------------------------------------------
// Launch 4. O2 = P @ Z via mma.sync bf16, 3-pass split, ratio fused.
// (round-6 proven, unchanged)
// ---------------------------------------------------------------------------
__global__ __launch_bounds__(256, 1)
void aft_mma(float* __restrict__ out)
{
    __shared__ __align__(128) char stg[2][16384];
    __shared__ float den[64][34];

    const int tid  = threadIdx.x;
    const int wid  = tid >> 5, lane = tid & 31;
    const int mw   = wid >> 2, nw = wid & 3;

    const int d0 = blockIdx.x * 32;
    const int m0 = blockIdx.y * 64;
    const int b  = blockIdx.z;

    const uint32_t sm0 = smem_u32(stg[0]);
    const uint32_t sm1 = smem_u32(stg[1]);

    const int am  = (lane & 7) + ((lane >> 3) & 1) * 8;
    const int akb = (lane >> 4) * 8;
    const int bn  = (lane & 7) + ((lane >> 4) & 1) * 8;
    const int bkb = ((lane >> 3) & 1) * 8;

    float c[2][2][4] = {};

    auto load_stage = [&](int s) {
        const uint32_t sb = (s & 1) ? sm1 : sm0;
        const int k0 = s * 32;
        #pragma unroll
        for (int i = 0; i < 4; i++) {
            int cch  = tid + i * 256;
            int tile = cch >> 8;
            int cc   = cch & 255;
            int row  = cc >> 2, c16 = cc & 3;
            uint32_t so = sb + tile * 4096 + SWZ64(row * 64 + c16 * 16);
            const __nv_bfloat16* src;
            int grow;
            if (tile < 2) {
                grow = m0 + row;
                src = (tile == 0) ? g_Ph : g_Pl;
            } else {
                int rowZ = (row < 32) ? d0 + row : 96 + d0 + row;
                grow = b * ZN + rowZ;
                src = (tile == 2) ? g_Zth : g_Ztl;
            }
            cpa16(so, src + (size_t)grow * SEQ + k0 + c16 * 8);
        }
        asm volatile("cp.async.commit_group;" ::: "memory");
    };

    load_stage(0);

    for (int s = 0; s < 16; s++) {
        asm volatile("cp.async.wait_group 0;" ::: "memory");
        __syncthreads();
        if (s < 15) load_stage(s + 1);
        const uint32_t sb = (s & 1) ? sm1 : sm0;
        #pragma unroll
        for (int kk = 0; kk < 2; kk++) {
            uint32_t ah[2][4], al[2][4], bh[4], bl[4];
            #pragma unroll
            for (int ms = 0; ms < 2; ms++) {
                int rowA = mw * 32 + ms * 16 + am;
                uint32_t off = SWZ64(rowA * 64 + kk * 32 + akb * 2);
                ldsm4(ah[ms], sb + off);
                ldsm4(al[ms], sb + 4096 + off);
            }
            {
                int rowB = nw * 16 + bn;
                uint32_t off = SWZ64(rowB * 64 + kk * 32 + bkb * 2);
                ldsm4(bh, sb + 8192 + off);
                ldsm4(bl, sb + 12288 + off);
            }
            #pragma unroll
            for (int ms = 0; ms < 2; ms++)
                #pragma unroll
                for (int ns = 0; ns < 2; ns++) {
                    mma16816(c[ms][ns], ah[ms], bh + 2 * ns);
                    mma16816(c[ms][ns], ah[ms], bl + 2 * ns);
                    mma16816(c[ms][ns], al[ms], bh + 2 * ns);
                }
        }
        __syncthreads();
    }

    if (nw >= 2) {
        #pragma unroll
        for (int ms = 0; ms < 2; ms++)
            #pragma unroll
            for (int ns = 0; ns < 2; ns++) {
                int dr = (nw - 2) * 16 + ns * 8 + 2 * (lane & 3);
                int r  = mw * 32 + ms * 16 + (lane >> 2);
                *(float2*)&den[r][dr]     = make_float2(c[ms][ns][0], c[ms][ns][1]);
                *(float2*)&den[r + 8][dr] = make_float2(c[ms][ns][2], c[ms][ns][3]);
            }
    }
    __syncthreads();
    if (nw < 2) {
        #pragma unroll
        for (int ms = 0; ms < 2; ms++)
            #pragma unroll
            for (int ns = 0; ns < 2; ns++) {
                int dr = nw * 16 + ns * 8 + 2 * (lane & 3);
                int r  = mw * 32 + ms * 16 + (lane >> 2);
                #pragma unroll
                for (int h = 0; h < 2; h++) {
                    int rr   = r + h * 8;
                    int grow = b * SEQ + m0 + rr;
                    float2 dn = *(float2*)&den[rr][dr];
                    float2 q  = *(const float2*)&g_q[(size_t)grow * DIM + d0 + dr];
                    float2 o;
                    o.x = q.x * c[ms][ns][2 * h]     / dn.x;
                    o.y = q.y * c[ms][ns][2 * h + 1] / dn.y;
                    *(float2*)&out[(size_t)grow * DIM + d0 + dr] = o;
                }
            }
    }
}

// ---------------------------------------------------------------------------
extern "C" void kernel_launch(void* const* d_in, const int* in_sizes, int n_in,
                              void* d_out, int out_size)
{
    const float* x   = (const float*)d_in[0];
    const float* Wq  = (const float*)d_in[1];
    const float* bq  = (const float*)d_in[2];
    const float* Wk  = (const float*)d_in[3];
    const float* bk  = (const float*)d_in[4];
    const float* Wv  = (const float*)d_in[5];
    const float* bv  = (const float*)d_in[6];
    const float* pos = (const float*)d_in[7];
    float* out = (float*)d_out;

    split_inputs<<<560, 256>>>(x, Wq, Wk, Wv, pos);
    proj_mma<<<dim3(4, 32), 256>>>(bq, bk, bv);
    transZ<<<dim3(4, 8, 4), 256>>>();
    aft_mma<<<dim3(4, 8, 4), 256>>>(out);
}

// round 9
// speedup vs baseline: 3.6064x; 1.0890x over previous
#include <cuda_runtime.h>
#include <cuda_bf16.h>
#include <math.h>
#include <stdint.h>

// AFT-full via separable exponent, all GEMMs on tensor cores (mma.sync bf16,
// 3-pass Markidis split):
//   L1 split_inputs: xh/xl, Wh/Wl (qkv concat), Ph/Pl = split(exp(pos))
//   L2 proj_mma:     qkv = x@W^T+b; epilogue: g_q=sigmoid(q), and DIRECTLY
//                    emits Zt hi/lo (transposed, bf16 split) — no transZ pass
//   L3 aft_mma:      O2 = P @ Z on HMMA (3-deep cp.async ring), ratio fused

#define BSZ   4
#define SEQ   512
#define DIM   128
#define NROW  (BSZ * SEQ)
#define ZN    256

typedef unsigned long long ull;

__device__ __align__(16) float         g_q  [NROW * DIM];
__device__ __align__(16) __nv_bfloat16 g_xh [NROW * DIM];
__device__ __align__(16) __nv_bfloat16 g_xl [NROW * DIM];
__device__ __align__(16) __nv_bfloat16 g_Wh [384 * DIM];
__device__ __align__(16) __nv_bfloat16 g_Wl [384 * DIM];
__device__ __align__(16) __nv_bfloat16 g_Ph [SEQ * SEQ];
__device__ __align__(16) __nv_bfloat16 g_Pl [SEQ * SEQ];
__device__ __align__(16) __nv_bfloat16 g_Zth[BSZ * ZN * SEQ];
__device__ __align__(16) __nv_bfloat16 g_Ztl[BSZ * ZN * SEQ];

// ---------------- portable PTX helpers (sm_80+ features only) --------------
__device__ __forceinline__ uint32_t smem_u32(const void* p) {
    uint32_t a;
    asm("{ .reg .u64 t; cvta.to.shared.u64 t, %1; cvt.u32.u64 %0, t; }" : "=r"(a) : "l"(p));
    return a;
}
#define SWZ64(x) ((x) ^ (((x) >> 3) & 0x30))

__device__ __forceinline__ void ldsm4(uint32_t* r, uint32_t addr) {
    asm volatile("ldmatrix.sync.aligned.m8n8.x4.shared.b16 {%0,%1,%2,%3}, [%4];"
        : "=r"(r[0]), "=r"(r[1]), "=r"(r[2]), "=r"(r[3]) : "r"(addr));
}
__device__ __forceinline__ void ldsm2(uint32_t* r, uint32_t addr) {
    asm volatile("ldmatrix.sync.aligned.m8n8.x2.shared.b16 {%0,%1}, [%2];"
        : "=r"(r[0]), "=r"(r[1]) : "r"(addr));
}
__device__ __forceinline__ void mma16816(float* c, const uint32_t* a, const uint32_t* b) {
    asm volatile("mma.sync.aligned.m16n8k16.row.col.f32.bf16.bf16.f32 "
        "{%0,%1,%2,%3}, {%4,%5,%6,%7}, {%8,%9}, {%0,%1,%2,%3};"
        : "+f"(c[0]), "+f"(c[1]), "+f"(c[2]), "+f"(c[3])
        : "r"(a[0]), "r"(a[1]), "r"(a[2]), "r"(a[3]), "r"(b[0]), "r"(b[1]));
}
__device__ __forceinline__ void cpa16(uint32_t s, const void* g) {
    asm volatile("cp.async.ca.shared.global [%0], [%1], 16;" :: "r"(s), "l"(g) : "memory");
}

__device__ __forceinline__ void split_store(__nv_bfloat16* H, __nv_bfloat16* L,
                                            size_t e, float4 v) {
    float a0 = v.x, a1 = v.y, a2 = v.z, a3 = v.w;
    __nv_bfloat16 h0 = __float2bfloat16(a0), h1 = __float2bfloat16(a1);
    __nv_bfloat16 h2 = __float2bfloat16(a2), h3 = __float2bfloat16(a3);
    __nv_bfloat16 l0 = __float2bfloat16(a0 - __bfloat162float(h0));
    __nv_bfloat16 l1 = __float2bfloat16(a1 - __bfloat162float(h1));
    __nv_bfloat16 l2 = __float2bfloat16(a2 - __bfloat162float(h2));
    __nv_bfloat16 l3 = __float2bfloat16(a3 - __bfloat162float(h3));
    *(__nv_bfloat162*)&H[e]     = __nv_bfloat162(h0, h1);
    *(__nv_bfloat162*)&H[e + 2] = __nv_bfloat162(h2, h3);
    *(__nv_bfloat162*)&L[e]     = __nv_bfloat162(l0, l1);
    *(__nv_bfloat162*)&L[e + 2] = __nv_bfloat162(l2, l3);
}

// ---------------------------------------------------------------------------
// Launch 1. Elementwise bf16 hi/lo splits: x, W(qkv concat), exp(pos).
// ---------------------------------------------------------------------------
__global__ __launch_bounds__(256)
void split_inputs(const float* __restrict__ x,
                  const float* __restrict__ Wq, const float* __restrict__ Wk,
                  const float* __restrict__ Wv, const float* __restrict__ pos)
{
    int idx = blockIdx.x * 256 + threadIdx.x;
    if (idx < 65536) {                      // x
        float4 v = ((const float4*)x)[idx];
        split_store(g_xh, g_xl, (size_t)idx * 4, v);
    } else if (idx < 131072) {              // exp(pos)
        int i = idx - 65536;
        float4 p = ((const float4*)pos)[i];
        float4 e;
        e.x = __expf(p.x); e.y = __expf(p.y); e.z = __expf(p.z); e.w = __expf(p.w);
        split_store(g_Ph, g_Pl, (size_t)i * 4, e);
    } else if (idx < 143360) {              // W concat
        int i = idx - 131072;
        int e = i * 4;
        int mat = e >> 14;
        int off = e & 16383;
        const float* W = (mat == 0) ? Wq : (mat == 1) ? Wk : Wv;
        float4 v = *(const float4*)&W[off];
        split_store(g_Wh, g_Wl, (size_t)e, v);
    }
}

// ---------------------------------------------------------------------------
// Launch 2. Projection GEMM on tensor cores (round-8 proven inner loop).
// CTA: 64m x 96n (matched q/k/v d-slice). Epilogue now emits g_q AND the
// transposed bf16-split Zt tiles directly (E/V held in SMEM).
// ---------------------------------------------------------------------------
__global__ __launch_bounds__(256, 1)
void proj_mma(const float* __restrict__ bq, const float* __restrict__ bk,
              const float* __restrict__ bv)
{
    __shared__ __align__(128) char arena[40960];

    const int tid = threadIdx.x;
    const int wid = tid >> 5, lane = tid & 31;
    const int mw  = wid >> 2, nw = wid & 3;
    const int d0  = blockIdx.x * 32;
    const int m0  = blockIdx.y * 64;

    const uint32_t sm0 = smem_u32(arena);
    const uint32_t sm1 = sm0 + 20480;

    const int am  = (lane & 7) + ((lane >> 3) & 1) * 8;
    const int akb = (lane >> 4) * 8;
    const int bn  = (lane & 7) + ((lane >> 4) & 1) * 8;
    const int bkb = ((lane >> 3) & 1) * 8;

    float c[2][3][4] = {};

    auto load_stage = [&](int s) {
        const uint32_t sb = (s & 1) ? sm1 : sm0;
        const int k0 = s * 32;
        #pragma unroll
        for (int i = 0; i < 5; i++) {
            int cch = tid + i * 256;
            const __nv_bfloat16* src;
            uint32_t so; size_t go;
            if (cch < 512) {
                int hl = cch >> 8, cc = cch & 255;
                int row = cc >> 2, c16 = cc & 3;
                so = sb + hl * 4096 + SWZ64(row * 64 + c16 * 16);
                src = hl ? g_xl : g_xh;
                go = (size_t)(m0 + row) * 128 + k0 + c16 * 8;
            } else {
                int v2 = cch - 512;
                int hl = v2 >= 384, cc = hl ? v2 - 384 : v2;
                int row = cc >> 2, c16 = cc & 3;
                so = sb + 8192 + hl * 6144 + SWZ64(row * 64 + c16 * 16);
                src = hl ? g_Wl : g_Wh;
                go = (size_t)((row >> 5) * 128 + d0 + (row & 31)) * 128 + k0 + c16 * 8;
            }
            cpa16(so, src + go);
        }
        asm volatile("cp.async.commit_group;" ::: "memory");
    };

    load_stage(0);

    for (int s = 0; s < 4; s++) {
        asm volatile("cp.async.wait_group 0;" ::: "memory");
        __syncthreads();
        if (s < 3) load_stage(s + 1);
        const uint32_t sb = (s & 1) ? sm1 : sm0;
        #pragma unroll
        for (int kk = 0; kk < 2; kk++) {
            uint32_t ah[2][4], al[2][4], bh[6], bl[6];
            #pragma unroll
            for (int ms = 0; ms < 2; ms++) {
                int rowA = mw * 32 + ms * 16 + am;
                uint32_t off = SWZ64(rowA * 64 + kk * 32 + akb * 2);
                ldsm4(ah[ms], sb + off);
                ldsm4(al[ms], sb + 4096 + off);
            }
            {
                int rowB = nw * 24 + bn;
                uint32_t off4 = SWZ64(rowB * 64 + kk * 32 + bkb * 2);
                ldsm4(bh, sb + 8192 + off4);
                ldsm4(bl, sb + 14336 + off4);
                int rowB2 = nw * 24 + 16 + (lane & 7);
                uint32_t off2 = SWZ64(rowB2 * 64 + kk * 32 + ((lane >> 3) & 1) * 16);
                ldsm2(bh + 4, sb + 8192 + off2);
                ldsm2(bl + 4, sb + 14336 + off2);
            }
            #pragma unroll
            for (int ms = 0; ms < 2; ms++)
                #pragma unroll
                for (int nf = 0; nf < 3; nf++) {
                    mma16816(c[ms][nf], ah[ms], bh + 2 * nf);
                    mma16816(c[ms][nf], ah[ms], bl + 2 * nf);
                    mma16816(c[ms][nf], al[ms], bh + 2 * nf);
                }
        }
        __syncthreads();
    }

    // ---- epilogue: E/V exchange in arena, then transposed split write ----
    float (*Ebuf)[33] = (float(*)[33])arena;
    float (*Vbuf)[33] = (float(*)[33])(arena + 8448);

    #pragma unroll
    for (int ms = 0; ms < 2; ms++)
        #pragma unroll
        for (int nf = 0; nf < 3; nf++) {
            int ncl = nw * 24 + nf * 8;
            int region = ncl >> 5;
            int dcol = (ncl & 31) + 2 * (lane & 3);
            int r0 = mw * 32 + ms * 16 + (lane >> 2);
            #pragma unroll
            for (int h = 0; h < 2; h++) {
                int r = r0 + 8 * h;
                float v0 = c[ms][nf][2 * h], v1 = c[ms][nf][2 * h + 1];
                int d = d0 + dcol;
                if (region == 0) {
                    float s0 = 1.0f / (1.0f + __expf(-(v0 + bq[d])));
                    float s1 = 1.0f / (1.0f + __expf(-(v1 + bq[d + 1])));
                    *(float2*)&g_q[(size_t)(m0 + r) * 128 + d] = make_float2(s0, s1);
                } else if (region == 1) {
                    Ebuf[r][dcol]     = __expf(v0 + bk[d]);
                    Ebuf[r][dcol + 1] = __expf(v1 + bk[d + 1]);
                } else {
                    Vbuf[r][dcol]     = v0 + bv[d];
                    Vbuf[r][dcol + 1] = v1 + bv[d + 1];
                }
            }
        }
    __syncthreads();

    // transposed, bf16 hi/lo split write: each thread owns (d, 8 j-values)
    {
        const int b  = m0 >> 9;
        const int j0 = m0 & 511;
        const int d  = tid >> 3;             // 0..31
        const int jl = (tid & 7) * 8;        // j local base
        __nv_bfloat16 nh[8], nl[8], dh[8], dl[8];
        #pragma unroll
        for (int i = 0; i < 8; i++) {
            float e = Ebuf[jl + i][d];
            float v = Vbuf[jl + i][d];
            float nm = e * v;
            nh[i] = __float2bfloat16(nm);
            nl[i] = __float2bfloat16(nm - __bfloat162float(nh[i]));
            dh[i] = __float2bfloat16(e);
            dl[i] = __float2bfloat16(e - __bfloat162float(dh[i]));
        }
        size_t rn = (size_t)(b * ZN + d0 + d) * SEQ + j0 + jl;
        size_t rd = (size_t)(b * ZN + 128 + d0 + d) * SEQ + j0 + jl;
        *(uint4*)&g_Zth[rn] = *(const uint4*)nh;
        *(uint4*)&g_Ztl[rn] = *(const uint4*)nl;
        *(uint4*)&g_Zth[rd] = *(const uint4*)dh;
        *(uint4*)&g_Ztl[rd] = *(const uint4*)dl;
    }
}

// ---------------------------------------------------------------------------
// Launch 3. O2 = P @ Z via mma.sync bf16, 3-pass split, ratio fused.
// 3-deep cp.async ring, wait_group 1, ONE __syncthreads per stage.
// SMEM: 3 x 16KB ring (48KB); den aliased into ring buffer 1 post-loop.
// ---------------------------------------------------------------------------
__global__ __launch_bounds__(256, 1)
void aft_mma(float* __restrict__ out)
{
    __shared__ __align__(128) char arena[49152];

    const int tid  = threadIdx.x;
    const int wid  = tid >> 5, lane = tid & 31;
    const int mw   = wid >> 2, nw = wid & 3;

    const int d0 = blockIdx.x * 32;
    const int m0 = blockIdx.y * 64;
    const int b  = blockIdx.z;

    const uint32_t sbase = smem_u32(arena);

    const int am  = (lane & 7) + ((lane >> 3) & 1) * 8;
    const int akb = (lane >> 4) * 8;
    const int bn  = (lane & 7) + ((lane >> 4) & 1) * 8;
    const int bkb = ((lane >> 3) & 1) * 8;

    float c[2][2][4] = {};

    auto load_stage = [&](int s) {
        const uint32_t sb = sbase + (uint32_t)(s % 3) * 16384;
        const int k0 = s * 32;
        #pragma unroll
        for (int i = 0; i < 4; i++) {
            int cch  = tid + i * 256;
            int tile = cch >> 8;
            int cc   = cch & 255;
            int row  = cc >> 2, c16 = cc & 3;
            uint32_t so = sb + tile * 4096 + SWZ64(row * 64 + c16 * 16);
            const __nv_bfloat16* src;
            int grow;
            if (tile < 2) {
                grow = m0 + row;
                src = (tile == 0) ? g_Ph : g_Pl;
            } else {
                int rowZ = (row < 32) ? d0 + row : 96 + d0 + row;
                grow = b * ZN + rowZ;
                src = (tile == 2) ? g_Zth : g_Ztl;
            }
            cpa16(so, src + (size_t)grow * SEQ + k0 + c16 * 8);
        }
        asm volatile("cp.async.commit_group;" ::: "memory");
    };

    load_stage(0);
    load_stage(1);

    for (int s = 0; s < 16; s++) {
        asm volatile("cp.async.wait_group 1;" ::: "memory");
        __syncthreads();
        if (s < 14) load_stage(s + 2);
        const uint32_t sb = sbase + (uint32_t)(s % 3) * 16384;
        #pragma unroll
        for (int kk = 0; kk < 2; kk++) {
            uint32_t ah[2][4], al[2][4], bh[4], bl[4];
            #pragma unroll
            for (int ms = 0; ms < 2; ms++) {
                int rowA = mw * 32 + ms * 16 + am;
                uint32_t off = SWZ64(rowA * 64 + kk * 32 + akb * 2);
                ldsm4(ah[ms], sb + off);
                ldsm4(al[ms], sb + 4096 + off);
            }
            {
                int rowB = nw * 16 + bn;
                uint32_t off = SWZ64(rowB * 64 + kk * 32 + bkb * 2);
                ldsm4(bh, sb + 8192 + off);
                ldsm4(bl, sb + 12288 + off);
            }
            #pragma unroll
            for (int ms = 0; ms < 2; ms++)
                #pragma unroll
                for (int ns = 0; ns < 2; ns++) {
                    mma16816(c[ms][ns], ah[ms], bh + 2 * ns);
                    mma16816(c[ms][ns], ah[ms], bl + 2 * ns);
                    mma16816(c[ms][ns], al[ms], bh + 2 * ns);
                }
        }
    }
    __syncthreads();

    // den exchange buffer aliased into ring buffer 1 (free after the loop)
    float (*den)[34] = (float(*)[34])(arena + 16384);

    if (nw >= 2) {
        #pragma unroll
        for (int ms = 0; ms < 2; ms++)
            #pragma unroll
            for (int ns = 0; ns < 2; ns++) {
                int dr = (nw - 2) * 16 + ns * 8 + 2 * (lane & 3);
                int r  = mw * 32 + ms * 16 + (lane >> 2);
                *(float2*)&den[r][dr]     = make_float2(c[ms][ns][0], c[ms][ns][1]);
                *(float2*)&den[r + 8][dr] = make_float2(c[ms][ns][2], c[ms][ns][3]);
            }
    }
    __syncthreads();
    if (nw < 2) {
        #pragma unroll
        for (int ms = 0; ms < 2; ms++)
            #pragma unroll
            for (int ns = 0; ns < 2; ns++) {
                int dr = nw * 16 + ns * 8 + 2 * (lane & 3);
                int r  = mw * 32 + ms * 16 + (lane >> 2);
                #pragma unroll
                for (int h = 0; h < 2; h++) {
                    int rr   = r + h * 8;
                    int grow = b * SEQ + m0 + rr;
                    float2 dn = *(float2*)&den[rr][dr];
                    float2 q  = *(const float2*)&g_q[(size_t)grow * DIM + d0 + dr];
                    float2 o;
                    o.x = q.x * c[ms][ns][2 * h]     / dn.x;
                    o.y = q.y * c[ms][ns][2 * h + 1] / dn.y;
                    *(float2*)&out[(size_t)grow * DIM + d0 + dr] = o;
                }
            }
    }
}

// ---------------------------------------------------------------------------
extern "C" void kernel_launch(void* const* d_in, const int* in_sizes, int n_in,
                              void* d_out, int out_size)
{
    const float* x   = (const float*)d_in[0];
    const float* Wq  = (const float*)d_in[1];
    const float* bq  = (const float*)d_in[2];
    const float* Wk  = (const float*)d_in[3];
    const float* bk  = (const float*)d_in[4];
    const float* Wv  = (const float*)d_in[5];
    const float* bv  = (const float*)d_in[6];
    const float* pos = (const float*)d_in[7];
    float* out = (float*)d_out;

    split_inputs<<<560, 256>>>(x, Wq, Wk, Wv, pos);
    proj_mma<<<dim3(4, 32), 256>>>(bq, bk, bv);
    aft_mma<<<dim3(4, 8, 4), 256>>>(out);
}